// round 1
// baseline (speedup 1.0000x reference)
#include <cuda_runtime.h>

// Problem constants
#define SQ   2048          // sequence length
#define DM   1024          // model dim
#define NH   16            // heads
#define HD   64            // head dim
#define NB   2             // batch
#define MT   (NB*SQ)       // 4096 rows total

// Scratch (device globals; no allocation allowed in kernel_launch)
__device__ float g_Q[NB*NH*SQ*HD];   // [B,H,S,HD]
__device__ float g_K[NB*NH*SQ*HD];
__device__ float g_V[NB*NH*SQ*HD];
__device__ float g_O[MT*DM];         // [B,S,D] attention output (pre out-proj)

// ---------------------------------------------------------------------------
// GEMM: C = A[M,K] @ W[N,K]^T + bias[N]
//   MODE 0: C row-major [M,N]
//   MODE 1: C head-split: row m=(b,s), col n=(h,dk) -> [((b*NH+h)*SQ+s)*HD+dk]
// Tiling: 128x128 block, BK=16, 256 threads, 8x8 per-thread (4+4 split).
// ---------------------------------------------------------------------------
template<int MODE>
__global__ void __launch_bounds__(256, 2)
gemm_kernel(const float* __restrict__ A, const float* __restrict__ W,
            const float* __restrict__ bias, float* __restrict__ C)
{
    __shared__ float As[16][128];
    __shared__ float Ws[16][128];

    const int tid = threadIdx.x;
    const int bm  = blockIdx.y * 128;
    const int bn  = blockIdx.x * 128;
    const int tr  = tid >> 4;          // 0..15
    const int tc  = tid & 15;          // 0..15
    const int lrow = tid >> 2;         // 0..63
    const int lk   = (tid & 3) << 2;   // 0,4,8,12

    const float* Ap0 = A + (size_t)(bm + lrow) * DM + lk;
    const float* Ap1 = Ap0 + (size_t)64 * DM;
    const float* Wp0 = W + (size_t)(bn + lrow) * DM + lk;
    const float* Wp1 = Wp0 + (size_t)64 * DM;

    float acc[8][8];
    #pragma unroll
    for (int i = 0; i < 8; i++)
        #pragma unroll
        for (int j = 0; j < 8; j++) acc[i][j] = 0.f;

    for (int k0 = 0; k0 < DM; k0 += 16) {
        float4 a0 = *(const float4*)(Ap0 + k0);
        float4 a1 = *(const float4*)(Ap1 + k0);
        float4 w0 = *(const float4*)(Wp0 + k0);
        float4 w1 = *(const float4*)(Wp1 + k0);
        __syncthreads();
        As[lk+0][lrow]    = a0.x; As[lk+1][lrow]    = a0.y;
        As[lk+2][lrow]    = a0.z; As[lk+3][lrow]    = a0.w;
        As[lk+0][lrow+64] = a1.x; As[lk+1][lrow+64] = a1.y;
        As[lk+2][lrow+64] = a1.z; As[lk+3][lrow+64] = a1.w;
        Ws[lk+0][lrow]    = w0.x; Ws[lk+1][lrow]    = w0.y;
        Ws[lk+2][lrow]    = w0.z; Ws[lk+3][lrow]    = w0.w;
        Ws[lk+0][lrow+64] = w1.x; Ws[lk+1][lrow+64] = w1.y;
        Ws[lk+2][lrow+64] = w1.z; Ws[lk+3][lrow+64] = w1.w;
        __syncthreads();

        #pragma unroll
        for (int k = 0; k < 16; k++) {
            float4 x0 = *(const float4*)&As[k][tr*4];
            float4 x1 = *(const float4*)&As[k][64 + tr*4];
            float4 y0 = *(const float4*)&Ws[k][tc*4];
            float4 y1 = *(const float4*)&Ws[k][64 + tc*4];
            float a[8] = {x0.x,x0.y,x0.z,x0.w, x1.x,x1.y,x1.z,x1.w};
            float b[8] = {y0.x,y0.y,y0.z,y0.w, y1.x,y1.y,y1.z,y1.w};
            #pragma unroll
            for (int i = 0; i < 8; i++)
                #pragma unroll
                for (int j = 0; j < 8; j++)
                    acc[i][j] = fmaf(a[i], b[j], acc[i][j]);
        }
    }

    // Epilogue: rows {bm+tr*4+i, bm+64+tr*4+i}, cols {bn+g*64+tc*4..+3}
    #pragma unroll
    for (int i = 0; i < 8; i++) {
        const int row = bm + tr*4 + ((i < 4) ? i : (60 + i));
        #pragma unroll
        for (int g = 0; g < 2; g++) {
            const int col = bn + g*64 + tc*4;
            float4 bb = *(const float4*)&bias[col];
            float4 r;
            r.x = acc[i][g*4+0] + bb.x;
            r.y = acc[i][g*4+1] + bb.y;
            r.z = acc[i][g*4+2] + bb.z;
            r.w = acc[i][g*4+3] + bb.w;
            if (MODE == 0) {
                *(float4*)&C[(size_t)row * DM + col] = r;
            } else {
                const int b_ = row >> 11;          // row / SQ
                const int s_ = row & (SQ - 1);
                const int h_ = col >> 6;           // col / HD
                const int dk = col & (HD - 1);
                *(float4*)&C[(((size_t)(b_*NH + h_) * SQ) + s_) * HD + dk] = r;
            }
        }
    }
}

// ---------------------------------------------------------------------------
// Flash attention (causal), fp32. One block = 64 query rows of one (b,h).
// One thread owns one query row: q row + output acc in registers,
// K/V tiles staged in smem (broadcast float4 reads). Online softmax.
// ---------------------------------------------------------------------------
__global__ void __launch_bounds__(64)
attn_kernel(const float* __restrict__ Q, const float* __restrict__ K,
            const float* __restrict__ V, float* __restrict__ O)
{
    __shared__ float4 Ks[1024];   // 64 rows x 16 float4
    __shared__ float4 Vs[1024];

    const int tid = threadIdx.x;       // query row within tile
    const int qt  = blockIdx.x;        // query tile
    const int h   = blockIdx.y;
    const int b   = blockIdx.z;

    const size_t headbase4 = (size_t)(b*NH + h) * SQ * (HD/4);
    const float4* Qh = (const float4*)Q + headbase4;
    const float4* Kh = (const float4*)K + headbase4;
    const float4* Vh = (const float4*)V + headbase4;

    // stage Q tile through Ks, then pull own row into registers
    for (int i = tid; i < 1024; i += 64) Ks[i] = Qh[qt*1024 + i];
    __syncthreads();
    float4 q[16];
    #pragma unroll
    for (int d = 0; d < 16; d++) q[d] = Ks[tid*16 + d];

    float4 acc[16];
    #pragma unroll
    for (int d = 0; d < 16; d++) acc[d] = make_float4(0.f, 0.f, 0.f, 0.f);
    float m = -1e30f, l = 0.f;

    for (int kt = 0; kt <= qt; kt++) {
        __syncthreads();   // previous tile fully consumed (also covers Q staging)
        for (int i = tid; i < 1024; i += 64) {
            Ks[i] = Kh[kt*1024 + i];
            Vs[i] = Vh[kt*1024 + i];
        }
        __syncthreads();

        const int jmax = (kt == qt) ? (tid + 1) : 64;   // causal
        for (int j = 0; j < jmax; j++) {
            float sx = 0.f, sy = 0.f, sz = 0.f, sw = 0.f;
            #pragma unroll
            for (int d = 0; d < 16; d++) {
                float4 kf = Ks[j*16 + d];
                sx = fmaf(q[d].x, kf.x, sx);
                sy = fmaf(q[d].y, kf.y, sy);
                sz = fmaf(q[d].z, kf.z, sz);
                sw = fmaf(q[d].w, kf.w, sw);
            }
            float s = ((sx + sy) + (sz + sw)) * 0.125f;   // 1/sqrt(64)

            if (s > m) {
                const float corr = __expf(m - s);
                m = s;
                l *= corr;
                #pragma unroll
                for (int d = 0; d < 16; d++) {
                    acc[d].x *= corr; acc[d].y *= corr;
                    acc[d].z *= corr; acc[d].w *= corr;
                }
            }
            const float p = __expf(s - m);
            l += p;
            #pragma unroll
            for (int d = 0; d < 16; d++) {
                float4 vf = Vs[j*16 + d];
                acc[d].x = fmaf(p, vf.x, acc[d].x);
                acc[d].y = fmaf(p, vf.y, acc[d].y);
                acc[d].z = fmaf(p, vf.z, acc[d].z);
                acc[d].w = fmaf(p, vf.w, acc[d].w);
            }
        }
    }

    const float inv = 1.f / l;
    const int srow = qt*64 + tid;
    float4* outp = (float4*)(O + ((size_t)b*SQ + srow) * DM + h*HD);
    #pragma unroll
    for (int d = 0; d < 16; d++) {
        float4 r = acc[d];
        r.x *= inv; r.y *= inv; r.z *= inv; r.w *= inv;
        outp[d] = r;
    }
}

// ---------------------------------------------------------------------------
// Launch: 3 projection GEMMs -> flash attention -> output GEMM
// Inputs (metadata order): query, key, value, mask(unused; tril causal),
//   w_q, b_q, w_k, b_k, w_v, b_v, w_out, b_out
// ---------------------------------------------------------------------------
extern "C" void kernel_launch(void* const* d_in, const int* in_sizes, int n_in,
                              void* d_out, int out_size)
{
    const float* query = (const float*)d_in[0];
    const float* key   = (const float*)d_in[1];
    const float* value = (const float*)d_in[2];
    const float* w_q   = (const float*)d_in[4];
    const float* b_q   = (const float*)d_in[5];
    const float* w_k   = (const float*)d_in[6];
    const float* b_k   = (const float*)d_in[7];
    const float* w_v   = (const float*)d_in[8];
    const float* b_v   = (const float*)d_in[9];
    const float* w_out = (const float*)d_in[10];
    const float* b_out = (const float*)d_in[11];

    float *Qp, *Kp, *Vp, *Op;
    cudaGetSymbolAddress((void**)&Qp, g_Q);
    cudaGetSymbolAddress((void**)&Kp, g_K);
    cudaGetSymbolAddress((void**)&Vp, g_V);
    cudaGetSymbolAddress((void**)&Op, g_O);

    dim3 ggrid(DM/128, MT/128);   // (8, 32)
    gemm_kernel<1><<<ggrid, 256>>>(query, w_q, b_q, Qp);
    gemm_kernel<1><<<ggrid, 256>>>(key,   w_k, b_k, Kp);
    gemm_kernel<1><<<ggrid, 256>>>(value, w_v, b_v, Vp);

    attn_kernel<<<dim3(SQ/64, NH, NB), 64>>>(Qp, Kp, Vp, Op);

    gemm_kernel<0><<<ggrid, 256>>>(Op, w_out, b_out, (float*)d_out);
}

// round 2
// speedup vs baseline: 1.4663x; 1.4663x over previous
#include <cuda_runtime.h>
#include <cstdint>

// Problem constants
#define SQ   2048          // sequence length
#define DM   1024          // model dim
#define NH   16            // heads
#define HD   64            // head dim
#define NB   2             // batch
#define MT   (NB*SQ)       // 4096 rows total

// Scratch (device globals; no allocation allowed in kernel_launch)
__device__ float g_Q[NB*NH*SQ*HD];   // [B,H,S,HD]
__device__ float g_K[NB*NH*SQ*HD];
__device__ float g_V[NB*NH*SQ*HD];
__device__ float g_O[MT*DM];         // [B,S,D] attention output (pre out-proj)

// ---------------------------------------------------------------------------
// tf32 helpers
// ---------------------------------------------------------------------------
__device__ __forceinline__ uint32_t f2tf(float f) {
    uint32_t u;
    asm("cvt.rna.tf32.f32 %0, %1;" : "=r"(u) : "f"(f));
    return u;
}

__device__ __forceinline__ void mma8(float& c0, float& c1, float& c2, float& c3,
                                     uint32_t a0, uint32_t a1, uint32_t a2, uint32_t a3,
                                     uint32_t b0, uint32_t b1) {
    asm("mma.sync.aligned.m16n8k8.row.col.f32.tf32.tf32.f32 "
        "{%0,%1,%2,%3}, {%4,%5,%6,%7}, {%8,%9}, {%0,%1,%2,%3};"
        : "+f"(c0), "+f"(c1), "+f"(c2), "+f"(c3)
        : "r"(a0), "r"(a1), "r"(a2), "r"(a3), "r"(b0), "r"(b1));
}

// ---------------------------------------------------------------------------
// tf32 tensor-core GEMM: C = A[M,K] @ W[N,K]^T + bias[N]
//   MODE 0: C row-major [M,N]
//   MODE 1: C head-split: row m=(b,s), col n=(h,dk) -> [((b*NH+h)*SQ+s)*HD+dk]
// Block tile 128x128, BK=32, 256 threads = 8 warps (2 M x 4 N),
// warp tile 64x32 = 4x4 m16n8k8 tiles. Smem row stride 36 floats ->
// fragment LDS bank = (4*row + k) mod 32, conflict-free.
// ---------------------------------------------------------------------------
#define SMS 36   // smem row stride in floats

template<int MODE>
__global__ void __launch_bounds__(256, 1)
gemm_tc_kernel(const float* __restrict__ A, const float* __restrict__ W,
               const float* __restrict__ bias, float* __restrict__ C)
{
    __shared__ uint32_t As[128 * SMS];
    __shared__ uint32_t Bs[128 * SMS];

    const int tid  = threadIdx.x;
    const int lane = tid & 31;
    const int wid  = tid >> 5;
    const int wm   = wid >> 2;        // 0..1  (M warp)
    const int wn   = wid & 3;         // 0..3  (N warp)
    const int lr   = lane >> 2;       // 0..7
    const int lk   = lane & 3;        // 0..3
    const int bm   = blockIdx.y * 128;
    const int bn   = blockIdx.x * 128;

    const int grow = tid >> 3;        // base row (0..31), +32 per i
    const int gf4  = tid & 7;         // float4 index within 32-float k-chunk

    float acc[4][4][4];
    #pragma unroll
    for (int mt = 0; mt < 4; mt++)
        #pragma unroll
        for (int nt = 0; nt < 4; nt++)
            #pragma unroll
            for (int r = 0; r < 4; r++) acc[mt][nt][r] = 0.f;

    float4 pa[4], pb[4];

    // prefetch tile 0
    #pragma unroll
    for (int i = 0; i < 4; i++) {
        const int row = grow + i * 32;
        pa[i] = *(const float4*)(A + (size_t)(bm + row) * DM + gf4 * 4);
        pb[i] = *(const float4*)(W + (size_t)(bn + row) * DM + gf4 * 4);
    }

    for (int t = 0; t < DM / 32; t++) {
        __syncthreads();   // previous tile fully consumed
        #pragma unroll
        for (int i = 0; i < 4; i++) {
            const int row = grow + i * 32;
            uint32_t* pA = &As[row * SMS + gf4 * 4];
            uint32_t* pB = &Bs[row * SMS + gf4 * 4];
            *(uint4*)pA = make_uint4(f2tf(pa[i].x), f2tf(pa[i].y), f2tf(pa[i].z), f2tf(pa[i].w));
            *(uint4*)pB = make_uint4(f2tf(pb[i].x), f2tf(pb[i].y), f2tf(pb[i].z), f2tf(pb[i].w));
        }
        __syncthreads();

        if (t + 1 < DM / 32) {
            const int k0 = (t + 1) * 32;
            #pragma unroll
            for (int i = 0; i < 4; i++) {
                const int row = grow + i * 32;
                pa[i] = *(const float4*)(A + (size_t)(bm + row) * DM + k0 + gf4 * 4);
                pb[i] = *(const float4*)(W + (size_t)(bn + row) * DM + k0 + gf4 * 4);
            }
        }

        #pragma unroll
        for (int kk = 0; kk < 4; kk++) {
            const int k = kk * 8;
            uint32_t af[4][4], bf[4][2];
            #pragma unroll
            for (int mt = 0; mt < 4; mt++) {
                const int row = wm * 64 + mt * 16 + lr;
                af[mt][0] = As[row * SMS + k + lk];
                af[mt][1] = As[(row + 8) * SMS + k + lk];
                af[mt][2] = As[row * SMS + k + 4 + lk];
                af[mt][3] = As[(row + 8) * SMS + k + 4 + lk];
            }
            #pragma unroll
            for (int nt = 0; nt < 4; nt++) {
                const int n = wn * 32 + nt * 8 + lr;
                bf[nt][0] = Bs[n * SMS + k + lk];
                bf[nt][1] = Bs[n * SMS + k + 4 + lk];
            }
            #pragma unroll
            for (int mt = 0; mt < 4; mt++)
                #pragma unroll
                for (int nt = 0; nt < 4; nt++)
                    mma8(acc[mt][nt][0], acc[mt][nt][1], acc[mt][nt][2], acc[mt][nt][3],
                         af[mt][0], af[mt][1], af[mt][2], af[mt][3],
                         bf[nt][0], bf[nt][1]);
        }
    }

    // Epilogue
    #pragma unroll
    for (int mt = 0; mt < 4; mt++) {
        const int row = bm + wm * 64 + mt * 16 + lr;
        #pragma unroll
        for (int nt = 0; nt < 4; nt++) {
            const int col = bn + wn * 32 + nt * 8 + 2 * lk;
            const float bx = bias[col];
            const float by = bias[col + 1];
            float2 r0 = make_float2(acc[mt][nt][0] + bx, acc[mt][nt][1] + by);
            float2 r1 = make_float2(acc[mt][nt][2] + bx, acc[mt][nt][3] + by);
            if (MODE == 0) {
                *(float2*)&C[(size_t)row * DM + col]       = r0;
                *(float2*)&C[(size_t)(row + 8) * DM + col] = r1;
            } else {
                const int h_  = col >> 6;
                const int dk  = col & (HD - 1);
                const int b0_ = row >> 11;
                const int s0_ = row & (SQ - 1);
                const int b1_ = (row + 8) >> 11;
                const int s1_ = (row + 8) & (SQ - 1);
                *(float2*)&C[(((size_t)(b0_ * NH + h_) * SQ) + s0_) * HD + dk] = r0;
                *(float2*)&C[(((size_t)(b1_ * NH + h_) * SQ) + s1_) * HD + dk] = r1;
            }
        }
    }
}

// ---------------------------------------------------------------------------
// Flash attention (causal), fp32. One block = 64 query rows of one (b,h).
// One thread owns one query row. qt reversed so longest blocks launch first.
// 2-key inner unroll for ILP + reduced softmax overhead.
// ---------------------------------------------------------------------------
__global__ void __launch_bounds__(64)
attn_kernel(const float* __restrict__ Q, const float* __restrict__ K,
            const float* __restrict__ V, float* __restrict__ O)
{
    __shared__ float4 Ks[1024];   // 64 rows x 16 float4
    __shared__ float4 Vs[1024];

    const int tid = threadIdx.x;                    // query row within tile
    const int qt  = (SQ / 64 - 1) - blockIdx.x;     // reversed: long blocks first
    const int h   = blockIdx.y;
    const int b   = blockIdx.z;

    const size_t headbase4 = (size_t)(b * NH + h) * SQ * (HD / 4);
    const float4* Qh = (const float4*)Q + headbase4;
    const float4* Kh = (const float4*)K + headbase4;
    const float4* Vh = (const float4*)V + headbase4;

    for (int i = tid; i < 1024; i += 64) Ks[i] = Qh[qt * 1024 + i];
    __syncthreads();
    float4 q[16];
    #pragma unroll
    for (int d = 0; d < 16; d++) q[d] = Ks[tid * 16 + d];

    float4 acc[16];
    #pragma unroll
    for (int d = 0; d < 16; d++) acc[d] = make_float4(0.f, 0.f, 0.f, 0.f);
    float m = -1e30f, l = 0.f;

    for (int kt = 0; kt <= qt; kt++) {
        __syncthreads();
        for (int i = tid; i < 1024; i += 64) {
            Ks[i] = Kh[kt * 1024 + i];
            Vs[i] = Vh[kt * 1024 + i];
        }
        __syncthreads();

        const int jmax = (kt == qt) ? (tid + 1) : 64;   // causal
        int j = 0;
        for (; j + 2 <= jmax; j += 2) {
            float s0x = 0.f, s0y = 0.f, s0z = 0.f, s0w = 0.f;
            float s1x = 0.f, s1y = 0.f, s1z = 0.f, s1w = 0.f;
            #pragma unroll
            for (int d = 0; d < 16; d++) {
                float4 k0 = Ks[j * 16 + d];
                float4 k1 = Ks[(j + 1) * 16 + d];
                s0x = fmaf(q[d].x, k0.x, s0x); s0y = fmaf(q[d].y, k0.y, s0y);
                s0z = fmaf(q[d].z, k0.z, s0z); s0w = fmaf(q[d].w, k0.w, s0w);
                s1x = fmaf(q[d].x, k1.x, s1x); s1y = fmaf(q[d].y, k1.y, s1y);
                s1z = fmaf(q[d].z, k1.z, s1z); s1w = fmaf(q[d].w, k1.w, s1w);
            }
            const float s0 = ((s0x + s0y) + (s0z + s0w)) * 0.125f;
            const float s1 = ((s1x + s1y) + (s1z + s1w)) * 0.125f;

            const float smax = fmaxf(s0, s1);
            if (smax > m) {
                const float corr = __expf(m - smax);
                m = smax;
                l *= corr;
                #pragma unroll
                for (int d = 0; d < 16; d++) {
                    acc[d].x *= corr; acc[d].y *= corr;
                    acc[d].z *= corr; acc[d].w *= corr;
                }
            }
            const float p0 = __expf(s0 - m);
            const float p1 = __expf(s1 - m);
            l += p0 + p1;
            #pragma unroll
            for (int d = 0; d < 16; d++) {
                float4 v0 = Vs[j * 16 + d];
                float4 v1 = Vs[(j + 1) * 16 + d];
                acc[d].x = fmaf(p0, v0.x, fmaf(p1, v1.x, acc[d].x));
                acc[d].y = fmaf(p0, v0.y, fmaf(p1, v1.y, acc[d].y));
                acc[d].z = fmaf(p0, v0.z, fmaf(p1, v1.z, acc[d].z));
                acc[d].w = fmaf(p0, v0.w, fmaf(p1, v1.w, acc[d].w));
            }
        }
        if (j < jmax) {   // odd tail (diagonal tile)
            float sx = 0.f, sy = 0.f, sz = 0.f, sw = 0.f;
            #pragma unroll
            for (int d = 0; d < 16; d++) {
                float4 kf = Ks[j * 16 + d];
                sx = fmaf(q[d].x, kf.x, sx); sy = fmaf(q[d].y, kf.y, sy);
                sz = fmaf(q[d].z, kf.z, sz); sw = fmaf(q[d].w, kf.w, sw);
            }
            const float s = ((sx + sy) + (sz + sw)) * 0.125f;
            if (s > m) {
                const float corr = __expf(m - s);
                m = s;
                l *= corr;
                #pragma unroll
                for (int d = 0; d < 16; d++) {
                    acc[d].x *= corr; acc[d].y *= corr;
                    acc[d].z *= corr; acc[d].w *= corr;
                }
            }
            const float p = __expf(s - m);
            l += p;
            #pragma unroll
            for (int d = 0; d < 16; d++) {
                float4 vf = Vs[j * 16 + d];
                acc[d].x = fmaf(p, vf.x, acc[d].x);
                acc[d].y = fmaf(p, vf.y, acc[d].y);
                acc[d].z = fmaf(p, vf.z, acc[d].z);
                acc[d].w = fmaf(p, vf.w, acc[d].w);
            }
        }
    }

    const float inv = 1.f / l;
    const int srow = qt * 64 + tid;
    float4* outp = (float4*)(O + ((size_t)b * SQ + srow) * DM + h * HD);
    #pragma unroll
    for (int d = 0; d < 16; d++) {
        float4 r = acc[d];
        r.x *= inv; r.y *= inv; r.z *= inv; r.w *= inv;
        outp[d] = r;
    }
}

// ---------------------------------------------------------------------------
// Launch: 3 projection GEMMs -> flash attention -> output GEMM
// Inputs (metadata order): query, key, value, mask(unused; tril causal),
//   w_q, b_q, w_k, b_k, w_v, b_v, w_out, b_out
// ---------------------------------------------------------------------------
extern "C" void kernel_launch(void* const* d_in, const int* in_sizes, int n_in,
                              void* d_out, int out_size)
{
    const float* query = (const float*)d_in[0];
    const float* key   = (const float*)d_in[1];
    const float* value = (const float*)d_in[2];
    const float* w_q   = (const float*)d_in[4];
    const float* b_q   = (const float*)d_in[5];
    const float* w_k   = (const float*)d_in[6];
    const float* b_k   = (const float*)d_in[7];
    const float* w_v   = (const float*)d_in[8];
    const float* b_v   = (const float*)d_in[9];
    const float* w_out = (const float*)d_in[10];
    const float* b_out = (const float*)d_in[11];

    float *Qp, *Kp, *Vp, *Op;
    cudaGetSymbolAddress((void**)&Qp, g_Q);
    cudaGetSymbolAddress((void**)&Kp, g_K);
    cudaGetSymbolAddress((void**)&Vp, g_V);
    cudaGetSymbolAddress((void**)&Op, g_O);

    dim3 ggrid(DM / 128, MT / 128);   // (8, 32)
    gemm_tc_kernel<1><<<ggrid, 256>>>(query, w_q, b_q, Qp);
    gemm_tc_kernel<1><<<ggrid, 256>>>(key,   w_k, b_k, Kp);
    gemm_tc_kernel<1><<<ggrid, 256>>>(value, w_v, b_v, Vp);

    attn_kernel<<<dim3(SQ / 64, NH, NB), 64>>>(Qp, Kp, Vp, Op);

    gemm_tc_kernel<0><<<ggrid, 256>>>(Op, w_out, b_out, (float*)d_out);
}

// round 5
// speedup vs baseline: 2.6816x; 1.8289x over previous
#include <cuda_runtime.h>
#include <cstdint>

// Problem constants
#define SQ   2048          // sequence length
#define DM   1024          // model dim
#define NH   16            // heads
#define HD   64            // head dim
#define NB   2             // batch
#define MT   (NB*SQ)       // 4096 rows total

// Scratch (device globals; no allocation allowed in kernel_launch)
__device__ float g_Q[NB*NH*SQ*HD];   // [B,H,S,HD]
__device__ float g_K[NB*NH*SQ*HD];
__device__ float g_V[NB*NH*SQ*HD];
__device__ float g_O[MT*DM];         // [B,S,D] attention output (pre out-proj)

// ---------------------------------------------------------------------------
// tf32 helpers
// ---------------------------------------------------------------------------
__device__ __forceinline__ uint32_t f2tf(float f) {
    uint32_t u;
    asm("cvt.rna.tf32.f32 %0, %1;" : "=r"(u) : "f"(f));
    return u;
}

__device__ __forceinline__ void mma8(float& c0, float& c1, float& c2, float& c3,
                                     uint32_t a0, uint32_t a1, uint32_t a2, uint32_t a3,
                                     uint32_t b0, uint32_t b1) {
    asm("mma.sync.aligned.m16n8k8.row.col.f32.tf32.tf32.f32 "
        "{%0,%1,%2,%3}, {%4,%5,%6,%7}, {%8,%9}, {%0,%1,%2,%3};"
        : "+f"(c0), "+f"(c1), "+f"(c2), "+f"(c3)
        : "r"(a0), "r"(a1), "r"(a2), "r"(a3), "r"(b0), "r"(b1));
}

// ---------------------------------------------------------------------------
// tf32 tensor-core GEMM: C = A[M,K] @ W[N,K]^T + bias[N]
//   MODE 0: C row-major [M,N]
//   MODE 1: C head-split: row m=(b,s), col n=(h,dk) -> [((b*NH+h)*SQ+s)*HD+dk]
// Block tile 128x128, BK=32, 256 threads = 8 warps (2 M x 4 N),
// warp tile 64x32 = 4x4 m16n8k8 tiles. Smem row stride 36 floats ->
// fragment LDS bank = (4*row + k) mod 32, conflict-free.
// ---------------------------------------------------------------------------
#define SMS 36   // smem row stride in floats

template<int MODE>
__global__ void __launch_bounds__(256, 1)
gemm_tc_kernel(const float* __restrict__ A, const float* __restrict__ W,
               const float* __restrict__ bias, float* __restrict__ C)
{
    __shared__ uint32_t As[128 * SMS];
    __shared__ uint32_t Bs[128 * SMS];

    const int tid  = threadIdx.x;
    const int lane = tid & 31;
    const int wid  = tid >> 5;
    const int wm   = wid >> 2;        // 0..1  (M warp)
    const int wn   = wid & 3;         // 0..3  (N warp)
    const int lr   = lane >> 2;       // 0..7
    const int lk   = lane & 3;        // 0..3
    const int bm   = blockIdx.y * 128;
    const int bn   = blockIdx.x * 128;

    const int grow = tid >> 3;        // base row (0..31), +32 per i
    const int gf4  = tid & 7;         // float4 index within 32-float k-chunk

    float acc[4][4][4];
    #pragma unroll
    for (int mt = 0; mt < 4; mt++)
        #pragma unroll
        for (int nt = 0; nt < 4; nt++)
            #pragma unroll
            for (int r = 0; r < 4; r++) acc[mt][nt][r] = 0.f;

    float4 pa[4], pb[4];

    // prefetch tile 0
    #pragma unroll
    for (int i = 0; i < 4; i++) {
        const int row = grow + i * 32;
        pa[i] = *(const float4*)(A + (size_t)(bm + row) * DM + gf4 * 4);
        pb[i] = *(const float4*)(W + (size_t)(bn + row) * DM + gf4 * 4);
    }

    for (int t = 0; t < DM / 32; t++) {
        __syncthreads();
        #pragma unroll
        for (int i = 0; i < 4; i++) {
            const int row = grow + i * 32;
            uint32_t* pA = &As[row * SMS + gf4 * 4];
            uint32_t* pB = &Bs[row * SMS + gf4 * 4];
            *(uint4*)pA = make_uint4(f2tf(pa[i].x), f2tf(pa[i].y), f2tf(pa[i].z), f2tf(pa[i].w));
            *(uint4*)pB = make_uint4(f2tf(pb[i].x), f2tf(pb[i].y), f2tf(pb[i].z), f2tf(pb[i].w));
        }
        __syncthreads();

        if (t + 1 < DM / 32) {
            const int k0 = (t + 1) * 32;
            #pragma unroll
            for (int i = 0; i < 4; i++) {
                const int row = grow + i * 32;
                pa[i] = *(const float4*)(A + (size_t)(bm + row) * DM + k0 + gf4 * 4);
                pb[i] = *(const float4*)(W + (size_t)(bn + row) * DM + k0 + gf4 * 4);
            }
        }

        #pragma unroll
        for (int kk = 0; kk < 4; kk++) {
            const int k = kk * 8;
            uint32_t af[4][4], bf[4][2];
            #pragma unroll
            for (int mt = 0; mt < 4; mt++) {
                const int row = wm * 64 + mt * 16 + lr;
                af[mt][0] = As[row * SMS + k + lk];
                af[mt][1] = As[(row + 8) * SMS + k + lk];
                af[mt][2] = As[row * SMS + k + 4 + lk];
                af[mt][3] = As[(row + 8) * SMS + k + 4 + lk];
            }
            #pragma unroll
            for (int nt = 0; nt < 4; nt++) {
                const int n = wn * 32 + nt * 8 + lr;
                bf[nt][0] = Bs[n * SMS + k + lk];
                bf[nt][1] = Bs[n * SMS + k + 4 + lk];
            }
            #pragma unroll
            for (int mt = 0; mt < 4; mt++)
                #pragma unroll
                for (int nt = 0; nt < 4; nt++)
                    mma8(acc[mt][nt][0], acc[mt][nt][1], acc[mt][nt][2], acc[mt][nt][3],
                         af[mt][0], af[mt][1], af[mt][2], af[mt][3],
                         bf[nt][0], bf[nt][1]);
        }
    }

    // Epilogue
    #pragma unroll
    for (int mt = 0; mt < 4; mt++) {
        const int row = bm + wm * 64 + mt * 16 + lr;
        #pragma unroll
        for (int nt = 0; nt < 4; nt++) {
            const int col = bn + wn * 32 + nt * 8 + 2 * lk;
            const float bx = bias[col];
            const float by = bias[col + 1];
            float2 r0 = make_float2(acc[mt][nt][0] + bx, acc[mt][nt][1] + by);
            float2 r1 = make_float2(acc[mt][nt][2] + bx, acc[mt][nt][3] + by);
            if (MODE == 0) {
                *(float2*)&C[(size_t)row * DM + col]       = r0;
                *(float2*)&C[(size_t)(row + 8) * DM + col] = r1;
            } else {
                const int h_  = col >> 6;
                const int dk  = col & (HD - 1);
                const int b0_ = row >> 11;
                const int s0_ = row & (SQ - 1);
                const int b1_ = (row + 8) >> 11;
                const int s1_ = (row + 8) & (SQ - 1);
                *(float2*)&C[(((size_t)(b0_ * NH + h_) * SQ) + s0_) * HD + dk] = r0;
                *(float2*)&C[(((size_t)(b1_ * NH + h_) * SQ) + s1_) * HD + dk] = r1;
            }
        }
    }
}

// ---------------------------------------------------------------------------
// Tensor-core flash attention (causal), tf32 mma with split-precision QK^T.
// Block = 128 q-rows of one (b,h); 8 warps, 16 rows each; key tiles of 64.
// K stored hi+lo in smem (stride 68), V tf32 (stride 72): fragment LDS
// conflict-free. P relayout acc->A-frag done with in-quad shuffles.
// ---------------------------------------------------------------------------
#define KST 68   // K smem row stride (floats):  bank = 4*lr + lk  (bijective)
#define VST 72   // V smem row stride (floats):  bank = 8*lk + lr  (bijective)
#define ATTN_SMEM ((64*KST*2 + 64*VST) * 4)

__global__ void __launch_bounds__(256, 1)
attn_tc_kernel(const float* __restrict__ Q, const float* __restrict__ K,
               const float* __restrict__ V, float* __restrict__ O)
{
    extern __shared__ uint32_t smem[];
    uint32_t* Kh = smem;                 // 64 x KST  (tf32 hi)
    uint32_t* Kl = smem + 64 * KST;      // 64 x KST  (tf32 residual)
    uint32_t* Vs = smem + 64 * KST * 2;  // 64 x VST  (tf32)

    const int tid  = threadIdx.x;
    const int lane = tid & 31;
    const int w    = tid >> 5;           // warp 0..7
    const int lr   = lane >> 2;          // group id 0..7
    const int lk   = lane & 3;           // thread-in-group 0..3

    const int qblk = (SQ / 128 - 1) - blockIdx.x;   // reversed: long blocks first
    const int h    = blockIdx.y;
    const int b    = blockIdx.z;
    const int qbase = qblk * 128;

    const size_t headbase = (size_t)(b * NH + h) * SQ * HD;
    const float* Qg = Q + headbase;
    const float* Kg = K + headbase;
    const float* Vg = V + headbase;

    // --- Q fragments (persistent, hi+lo split), rows w*16 + {lr, lr+8} ---
    const int r0 = qbase + w * 16 + lr;
    uint32_t qh[8][4], ql[8][4];
    #pragma unroll
    for (int kk = 0; kk < 8; kk++) {
        float x0 = Qg[(size_t)r0 * HD + kk * 8 + lk];
        float x1 = Qg[(size_t)(r0 + 8) * HD + kk * 8 + lk];
        float x2 = Qg[(size_t)r0 * HD + kk * 8 + 4 + lk];
        float x3 = Qg[(size_t)(r0 + 8) * HD + kk * 8 + 4 + lk];
        qh[kk][0] = f2tf(x0); ql[kk][0] = f2tf(x0 - __uint_as_float(qh[kk][0]));
        qh[kk][1] = f2tf(x1); ql[kk][1] = f2tf(x1 - __uint_as_float(qh[kk][1]));
        qh[kk][2] = f2tf(x2); ql[kk][2] = f2tf(x2 - __uint_as_float(qh[kk][2]));
        qh[kk][3] = f2tf(x3); ql[kk][3] = f2tf(x3 - __uint_as_float(qh[kk][3]));
    }

    float oacc[8][4];
    #pragma unroll
    for (int nt = 0; nt < 8; nt++)
        #pragma unroll
        for (int r = 0; r < 4; r++) oacc[nt][r] = 0.f;

    float m0 = -1e30f, m1 = -1e30f, l0 = 0.f, l1 = 0.f;

    const int ntiles = 2 * qblk + 2;
    for (int kt = 0; kt < ntiles; kt++) {
        __syncthreads();
        // stage K (hi+lo) and V (tf32) tiles: 64x64 each
        #pragma unroll
        for (int i = 0; i < 4; i++) {
            const int idx = tid + i * 256;           // 0..1023 float4 slots
            const int row = idx >> 4;
            const int c4  = (idx & 15) * 4;
            float4 kv = *(const float4*)&Kg[(size_t)(kt * 64 + row) * HD + c4];
            float4 vv = *(const float4*)&Vg[(size_t)(kt * 64 + row) * HD + c4];
            uint32_t hx = f2tf(kv.x), hy = f2tf(kv.y), hz = f2tf(kv.z), hw = f2tf(kv.w);
            *(uint4*)&Kh[row * KST + c4] = make_uint4(hx, hy, hz, hw);
            *(uint4*)&Kl[row * KST + c4] = make_uint4(
                f2tf(kv.x - __uint_as_float(hx)), f2tf(kv.y - __uint_as_float(hy)),
                f2tf(kv.z - __uint_as_float(hz)), f2tf(kv.w - __uint_as_float(hw)));
            *(uint4*)&Vs[row * VST + c4] = make_uint4(f2tf(vv.x), f2tf(vv.y),
                                                      f2tf(vv.z), f2tf(vv.w));
        }
        __syncthreads();

        // --- S = Q K^T (split tf32: qh*kh + qh*kl + ql*kh) ---
        float sacc[8][4];
        #pragma unroll
        for (int nt = 0; nt < 8; nt++)
            #pragma unroll
            for (int r = 0; r < 4; r++) sacc[nt][r] = 0.f;

        #pragma unroll
        for (int kk = 0; kk < 8; kk++) {
            #pragma unroll
            for (int nt = 0; nt < 8; nt++) {
                const int krow = nt * 8 + lr;
                uint32_t kb0 = Kh[krow * KST + kk * 8 + lk];
                uint32_t kb1 = Kh[krow * KST + kk * 8 + 4 + lk];
                uint32_t lb0 = Kl[krow * KST + kk * 8 + lk];
                uint32_t lb1 = Kl[krow * KST + kk * 8 + 4 + lk];
                mma8(sacc[nt][0], sacc[nt][1], sacc[nt][2], sacc[nt][3],
                     qh[kk][0], qh[kk][1], qh[kk][2], qh[kk][3], kb0, kb1);
                mma8(sacc[nt][0], sacc[nt][1], sacc[nt][2], sacc[nt][3],
                     qh[kk][0], qh[kk][1], qh[kk][2], qh[kk][3], lb0, lb1);
                mma8(sacc[nt][0], sacc[nt][1], sacc[nt][2], sacc[nt][3],
                     ql[kk][0], ql[kk][1], ql[kk][2], ql[kk][3], kb0, kb1);
            }
        }

        // --- scale + causal mask ---
        const bool may_mask = (kt * 64 + 63 > qbase);
        #pragma unroll
        for (int nt = 0; nt < 8; nt++) {
            const int c = kt * 64 + nt * 8 + 2 * lk;
            #pragma unroll
            for (int r = 0; r < 4; r++) sacc[nt][r] *= 0.125f;
            if (may_mask) {
                if (c     > r0)     sacc[nt][0] = -1e30f;
                if (c + 1 > r0)     sacc[nt][1] = -1e30f;
                if (c     > r0 + 8) sacc[nt][2] = -1e30f;
                if (c + 1 > r0 + 8) sacc[nt][3] = -1e30f;
            }
        }

        // --- online softmax (rows r0 and r0+8) ---
        float tm0 = -1e30f, tm1 = -1e30f;
        #pragma unroll
        for (int nt = 0; nt < 8; nt++) {
            tm0 = fmaxf(tm0, fmaxf(sacc[nt][0], sacc[nt][1]));
            tm1 = fmaxf(tm1, fmaxf(sacc[nt][2], sacc[nt][3]));
        }
        tm0 = fmaxf(tm0, __shfl_xor_sync(0xffffffff, tm0, 1));
        tm0 = fmaxf(tm0, __shfl_xor_sync(0xffffffff, tm0, 2));
        tm1 = fmaxf(tm1, __shfl_xor_sync(0xffffffff, tm1, 1));
        tm1 = fmaxf(tm1, __shfl_xor_sync(0xffffffff, tm1, 2));

        const float mn0 = fmaxf(m0, tm0);
        const float mn1 = fmaxf(m1, tm1);
        const float cor0 = __expf(m0 - mn0);
        const float cor1 = __expf(m1 - mn1);
        m0 = mn0; m1 = mn1;

        float sum0 = 0.f, sum1 = 0.f;
        #pragma unroll
        for (int nt = 0; nt < 8; nt++) {
            sacc[nt][0] = __expf(sacc[nt][0] - m0);
            sacc[nt][1] = __expf(sacc[nt][1] - m0);
            sacc[nt][2] = __expf(sacc[nt][2] - m1);
            sacc[nt][3] = __expf(sacc[nt][3] - m1);
            sum0 += sacc[nt][0] + sacc[nt][1];
            sum1 += sacc[nt][2] + sacc[nt][3];
        }
        sum0 += __shfl_xor_sync(0xffffffff, sum0, 1);
        sum0 += __shfl_xor_sync(0xffffffff, sum0, 2);
        sum1 += __shfl_xor_sync(0xffffffff, sum1, 1);
        sum1 += __shfl_xor_sync(0xffffffff, sum1, 2);
        l0 = l0 * cor0 + sum0;
        l1 = l1 * cor1 + sum1;

        #pragma unroll
        for (int nt = 0; nt < 8; nt++) {
            oacc[nt][0] *= cor0; oacc[nt][1] *= cor0;
            oacc[nt][2] *= cor1; oacc[nt][3] *= cor1;
        }

        // --- O += P V ---
        const int s0 = (lane & ~3) | (lk >> 1);   // src lane for cols lk
        const int s2 = s0 + 2;                    // src lane for cols lk+4
        const int par = lk & 1;
        #pragma unroll
        for (int kk = 0; kk < 8; kk++) {
            // rebuild A-fragment of P for this 8-key chunk via in-quad shuffles
            float v00 = __shfl_sync(0xffffffff, sacc[kk][0], s0);
            float v01 = __shfl_sync(0xffffffff, sacc[kk][1], s0);
            float v20 = __shfl_sync(0xffffffff, sacc[kk][0], s2);
            float v21 = __shfl_sync(0xffffffff, sacc[kk][1], s2);
            float v10 = __shfl_sync(0xffffffff, sacc[kk][2], s0);
            float v11 = __shfl_sync(0xffffffff, sacc[kk][3], s0);
            float v30 = __shfl_sync(0xffffffff, sacc[kk][2], s2);
            float v31 = __shfl_sync(0xffffffff, sacc[kk][3], s2);
            uint32_t a0 = f2tf(par ? v01 : v00);
            uint32_t a1 = f2tf(par ? v11 : v10);
            uint32_t a2 = f2tf(par ? v21 : v20);
            uint32_t a3 = f2tf(par ? v31 : v30);

            #pragma unroll
            for (int nt = 0; nt < 8; nt++) {
                uint32_t vb0 = Vs[(kk * 8 + lk) * VST + nt * 8 + lr];
                uint32_t vb1 = Vs[(kk * 8 + 4 + lk) * VST + nt * 8 + lr];
                mma8(oacc[nt][0], oacc[nt][1], oacc[nt][2], oacc[nt][3],
                     a0, a1, a2, a3, vb0, vb1);
            }
        }
    }

    // --- write O: [b, s, h*64 + d] ---
    const float inv0 = 1.f / l0;
    const float inv1 = 1.f / l1;
    float* Ob0 = O + ((size_t)b * SQ + r0) * DM + h * HD;
    float* Ob1 = O + ((size_t)b * SQ + r0 + 8) * DM + h * HD;
    #pragma unroll
    for (int nt = 0; nt < 8; nt++) {
        const int c = nt * 8 + 2 * lk;
        *(float2*)&Ob0[c] = make_float2(oacc[nt][0] * inv0, oacc[nt][1] * inv0);
        *(float2*)&Ob1[c] = make_float2(oacc[nt][2] * inv1, oacc[nt][3] * inv1);
    }
}

// ---------------------------------------------------------------------------
// Launch: 3 projection GEMMs -> TC flash attention -> output GEMM
// Inputs (metadata order): query, key, value, mask(unused; tril causal),
//   w_q, b_q, w_k, b_k, w_v, b_v, w_out, b_out
// ---------------------------------------------------------------------------
extern "C" void kernel_launch(void* const* d_in, const int* in_sizes, int n_in,
                              void* d_out, int out_size)
{
    const float* query = (const float*)d_in[0];
    const float* key   = (const float*)d_in[1];
    const float* value = (const float*)d_in[2];
    const float* w_q   = (const float*)d_in[4];
    const float* b_q   = (const float*)d_in[5];
    const float* w_k   = (const float*)d_in[6];
    const float* b_k   = (const float*)d_in[7];
    const float* w_v   = (const float*)d_in[8];
    const float* b_v   = (const float*)d_in[9];
    const float* w_out = (const float*)d_in[10];
    const float* b_out = (const float*)d_in[11];

    float *Qp, *Kp, *Vp, *Op;
    cudaGetSymbolAddress((void**)&Qp, g_Q);
    cudaGetSymbolAddress((void**)&Kp, g_K);
    cudaGetSymbolAddress((void**)&Vp, g_V);
    cudaGetSymbolAddress((void**)&Op, g_O);

    cudaFuncSetAttribute(attn_tc_kernel,
                         cudaFuncAttributeMaxDynamicSharedMemorySize, ATTN_SMEM);

    dim3 ggrid(DM / 128, MT / 128);   // (8, 32)
    gemm_tc_kernel<1><<<ggrid, 256>>>(query, w_q, b_q, Qp);
    gemm_tc_kernel<1><<<ggrid, 256>>>(key,   w_k, b_k, Kp);
    gemm_tc_kernel<1><<<ggrid, 256>>>(value, w_v, b_v, Vp);

    attn_tc_kernel<<<dim3(SQ / 128, NH, NB), 256, ATTN_SMEM>>>(Qp, Kp, Vp, Op);

    gemm_tc_kernel<0><<<ggrid, 256>>>(Op, w_out, b_out, (float*)d_out);
}

// round 7
// speedup vs baseline: 3.2679x; 1.2186x over previous
#include <cuda_runtime.h>
#include <cstdint>

// Problem constants
#define SQ   2048          // sequence length
#define DM   1024          // model dim
#define NH   16            // heads
#define HD   64            // head dim
#define NB   2             // batch
#define MT   (NB*SQ)       // 4096 rows total

// Scratch (device globals; no allocation allowed in kernel_launch)
__device__ float g_Q[NB*NH*SQ*HD];   // [B,H,S,HD]
__device__ float g_K[NB*NH*SQ*HD];
__device__ float g_V[NB*NH*SQ*HD];
__device__ float g_O[MT*DM];         // [B,S,D] attention output (pre out-proj)

// ---------------------------------------------------------------------------
// helpers
// ---------------------------------------------------------------------------
__device__ __forceinline__ uint32_t f2tf(float f) {
    uint32_t u;
    asm("cvt.rna.tf32.f32 %0, %1;" : "=r"(u) : "f"(f));
    return u;
}

__device__ __forceinline__ void mma8(float& c0, float& c1, float& c2, float& c3,
                                     uint32_t a0, uint32_t a1, uint32_t a2, uint32_t a3,
                                     uint32_t b0, uint32_t b1) {
    asm("mma.sync.aligned.m16n8k8.row.col.f32.tf32.tf32.f32 "
        "{%0,%1,%2,%3}, {%4,%5,%6,%7}, {%8,%9}, {%0,%1,%2,%3};"
        : "+f"(c0), "+f"(c1), "+f"(c2), "+f"(c3)
        : "r"(a0), "r"(a1), "r"(a2), "r"(a3), "r"(b0), "r"(b1));
}

// ldmatrix x4: four 8x4 b32 tiles; lane l gets, per tile, element (l>>2, l&3).
// Lanes 0-7 supply tile0 row addrs, 8-15 tile1, 16-23 tile2, 24-31 tile3.
__device__ __forceinline__ void ldsm4(uint32_t& r0, uint32_t& r1,
                                      uint32_t& r2, uint32_t& r3, uint32_t addr) {
    asm volatile("ldmatrix.sync.aligned.m8n8.x4.shared.b16 {%0,%1,%2,%3}, [%4];"
                 : "=r"(r0), "=r"(r1), "=r"(r2), "=r"(r3) : "r"(addr));
}

__device__ __forceinline__ uint32_t smem_u32(const void* p) {
    return (uint32_t)__cvta_generic_to_shared(p);
}

// ---------------------------------------------------------------------------
// tf32 tensor-core GEMM: C = A[M,K] @ W[N,K]^T + bias[N]
//   MODE 0: C row-major [M,N]
//   MODE 1: C head-split: row m=(b,s), col n=(h,dk) -> [((b*NH+h)*SQ+s)*HD+dk]
// 128x128 block, BK=32, 8 warps (2Mx4N), warp tile 64x32.
// Fragment loads via ldmatrix (6 LDSM per k-chunk instead of 24 LDS).
// ---------------------------------------------------------------------------
#define SMS 36   // smem row stride in floats (4*row+k bijective mod 32)

template<int MODE>
__global__ void __launch_bounds__(256, 1)
gemm_tc_kernel(const float* __restrict__ A, const float* __restrict__ W,
               const float* __restrict__ bias, float* __restrict__ C)
{
    __shared__ uint32_t As[128 * SMS];
    __shared__ uint32_t Bs[128 * SMS];

    const int tid  = threadIdx.x;
    const int lane = tid & 31;
    const int wid  = tid >> 5;
    const int wm   = wid >> 2;        // 0..1  (M warp)
    const int wn   = wid & 3;         // 0..3  (N warp)
    const int lr   = lane >> 2;       // 0..7
    const int lk   = lane & 3;        // 0..3
    const int seg  = lane >> 3;       // ldmatrix tile segment 0..3
    const int sr   = lane & 7;        // row within tile segment
    const int bm   = blockIdx.y * 128;
    const int bn   = blockIdx.x * 128;

    const int grow = tid >> 3;        // base row (0..31), +32 per i
    const int gf4  = tid & 7;         // float4 index within 32-float k-chunk

    // ldmatrix per-lane base addresses (bytes), k-part added per chunk.
    // A tiles: t0=(+0,k) t1=(+8,k) t2=(+0,k+4) t3=(+8,k+4):
    //   row += (seg&1)*8, col += (seg>>1)*4
    uint32_t aab[4];
    const uint32_t asBase = smem_u32(As);
    #pragma unroll
    for (int mt = 0; mt < 4; mt++)
        aab[mt] = asBase + (((wm * 64 + mt * 16 + (seg & 1) * 8 + sr) * SMS
                             + (seg >> 1) * 4) << 2);
    // B tiles (two nt per x4): t0=(nt,k) t1=(nt,k+4) t2=(nt+1,k) t3=(nt+1,k+4):
    //   row += (seg>>1)*8, col += (seg&1)*4
    uint32_t bab[2];
    const uint32_t bsBase = smem_u32(Bs);
    #pragma unroll
    for (int p = 0; p < 2; p++)
        bab[p] = bsBase + (((wn * 32 + p * 16 + (seg >> 1) * 8 + sr) * SMS
                            + (seg & 1) * 4) << 2);

    float acc[4][4][4];
    #pragma unroll
    for (int mt = 0; mt < 4; mt++)
        #pragma unroll
        for (int nt = 0; nt < 4; nt++)
            #pragma unroll
            for (int r = 0; r < 4; r++) acc[mt][nt][r] = 0.f;

    float4 pa[4], pb[4];

    // prefetch tile 0
    #pragma unroll
    for (int i = 0; i < 4; i++) {
        const int row = grow + i * 32;
        pa[i] = *(const float4*)(A + (size_t)(bm + row) * DM + gf4 * 4);
        pb[i] = *(const float4*)(W + (size_t)(bn + row) * DM + gf4 * 4);
    }

    for (int t = 0; t < DM / 32; t++) {
        __syncthreads();
        #pragma unroll
        for (int i = 0; i < 4; i++) {
            const int row = grow + i * 32;
            uint32_t* pA = &As[row * SMS + gf4 * 4];
            uint32_t* pB = &Bs[row * SMS + gf4 * 4];
            *(uint4*)pA = make_uint4(f2tf(pa[i].x), f2tf(pa[i].y), f2tf(pa[i].z), f2tf(pa[i].w));
            *(uint4*)pB = make_uint4(f2tf(pb[i].x), f2tf(pb[i].y), f2tf(pb[i].z), f2tf(pb[i].w));
        }
        __syncthreads();

        if (t + 1 < DM / 32) {
            const int k0 = (t + 1) * 32;
            #pragma unroll
            for (int i = 0; i < 4; i++) {
                const int row = grow + i * 32;
                pa[i] = *(const float4*)(A + (size_t)(bm + row) * DM + k0 + gf4 * 4);
                pb[i] = *(const float4*)(W + (size_t)(bn + row) * DM + k0 + gf4 * 4);
            }
        }

        #pragma unroll
        for (int kk = 0; kk < 4; kk++) {
            const uint32_t koff = kk * 32;   // 8 floats = 32 bytes
            uint32_t af[4][4], bf[4][2];
            #pragma unroll
            for (int mt = 0; mt < 4; mt++)
                ldsm4(af[mt][0], af[mt][1], af[mt][2], af[mt][3], aab[mt] + koff);
            ldsm4(bf[0][0], bf[0][1], bf[1][0], bf[1][1], bab[0] + koff);
            ldsm4(bf[2][0], bf[2][1], bf[3][0], bf[3][1], bab[1] + koff);
            #pragma unroll
            for (int mt = 0; mt < 4; mt++)
                #pragma unroll
                for (int nt = 0; nt < 4; nt++)
                    mma8(acc[mt][nt][0], acc[mt][nt][1], acc[mt][nt][2], acc[mt][nt][3],
                         af[mt][0], af[mt][1], af[mt][2], af[mt][3],
                         bf[nt][0], bf[nt][1]);
        }
    }

    // Epilogue
    #pragma unroll
    for (int mt = 0; mt < 4; mt++) {
        const int row = bm + wm * 64 + mt * 16 + lr;
        #pragma unroll
        for (int nt = 0; nt < 4; nt++) {
            const int col = bn + wn * 32 + nt * 8 + 2 * lk;
            const float bx = bias[col];
            const float by = bias[col + 1];
            float2 r0 = make_float2(acc[mt][nt][0] + bx, acc[mt][nt][1] + by);
            float2 r1 = make_float2(acc[mt][nt][2] + bx, acc[mt][nt][3] + by);
            if (MODE == 0) {
                *(float2*)&C[(size_t)row * DM + col]       = r0;
                *(float2*)&C[(size_t)(row + 8) * DM + col] = r1;
            } else {
                const int h_  = col >> 6;
                const int dk  = col & (HD - 1);
                const int b0_ = row >> 11;
                const int s0_ = row & (SQ - 1);
                const int b1_ = (row + 8) >> 11;
                const int s1_ = (row + 8) & (SQ - 1);
                *(float2*)&C[(((size_t)(b0_ * NH + h_) * SQ) + s0_) * HD + dk] = r0;
                *(float2*)&C[(((size_t)(b1_ * NH + h_) * SQ) + s1_) * HD + dk] = r1;
            }
        }
    }
}

// ---------------------------------------------------------------------------
// Tensor-core flash attention (causal), tf32 mma.
// QK^T split: qh*kh + qh*kl (K residual-compensated; Q single-rounded).
// Block = 128 q-rows of one (b,h); 8 warps, 16 rows each; key tiles of 64.
// K-fragment loads via ldmatrix; K/V tiles register-prefetched.
// ---------------------------------------------------------------------------
#define KST 68   // K smem row stride (floats) -> ldmatrix rows conflict-free
#define VST 72   // V smem row stride (floats):  bank = 8*lk + lr  (bijective)
#define ATTN_SMEM ((64*KST*2 + 64*VST) * 4)

__global__ void __launch_bounds__(256, 1)
attn_tc_kernel(const float* __restrict__ Q, const float* __restrict__ K,
               const float* __restrict__ V, float* __restrict__ O)
{
    extern __shared__ uint32_t smem[];
    uint32_t* Kh = smem;                 // 64 x KST  (tf32 hi)
    uint32_t* Kl = smem + 64 * KST;      // 64 x KST  (tf32 residual)
    uint32_t* Vs = smem + 64 * KST * 2;  // 64 x VST  (tf32)

    const int tid  = threadIdx.x;
    const int lane = tid & 31;
    const int w    = tid >> 5;           // warp 0..7
    const int lr   = lane >> 2;          // group id 0..7
    const int lk   = lane & 3;           // thread-in-group 0..3
    const int seg  = lane >> 3;
    const int sr   = lane & 7;

    const int qblk = (SQ / 128 - 1) - blockIdx.x;   // reversed: long blocks first
    const int h    = blockIdx.y;
    const int b    = blockIdx.z;
    const int qbase = qblk * 128;

    const size_t headbase = (size_t)(b * NH + h) * SQ * HD;
    const float* Qg = Q + headbase;
    const float* Kg = K + headbase;
    const float* Vg = V + headbase;

    // ldmatrix per-lane base addrs for K tiles (two nt per x4):
    //   t0=(nt,k) t1=(nt,k+4) t2=(nt+1,k) t3=(nt+1,k+4)
    uint32_t khb[4], klb[4];
    {
        const uint32_t khBase = smem_u32(Kh);
        #pragma unroll
        for (int p = 0; p < 4; p++) {
            const uint32_t off = (((p * 16 + (seg >> 1) * 8 + sr) * KST
                                   + (seg & 1) * 4) << 2);
            khb[p] = khBase + off;
            klb[p] = khBase + (64 * KST * 4) + off;
        }
    }

    // --- Q fragments (persistent, single tf32), rows w*16 + {lr, lr+8} ---
    const int r0 = qbase + w * 16 + lr;
    uint32_t qh[8][4];
    #pragma unroll
    for (int kk = 0; kk < 8; kk++) {
        qh[kk][0] = f2tf(Qg[(size_t)r0 * HD + kk * 8 + lk]);
        qh[kk][1] = f2tf(Qg[(size_t)(r0 + 8) * HD + kk * 8 + lk]);
        qh[kk][2] = f2tf(Qg[(size_t)r0 * HD + kk * 8 + 4 + lk]);
        qh[kk][3] = f2tf(Qg[(size_t)(r0 + 8) * HD + kk * 8 + 4 + lk]);
    }

    float oacc[8][4];
    #pragma unroll
    for (int nt = 0; nt < 8; nt++)
        #pragma unroll
        for (int r = 0; r < 4; r++) oacc[nt][r] = 0.f;

    float m0 = -1e30f, m1 = -1e30f, l0 = 0.f, l1 = 0.f;

    const int ntiles = 2 * qblk + 2;

    // staging slot for this thread
    const int strow = tid >> 4;          // +16 per i
    const int stc4  = (tid & 15) * 4;

    // prefetch tile 0 into registers
    float4 pk[4], pv[4];
    #pragma unroll
    for (int i = 0; i < 4; i++) {
        const int row = strow + i * 16;
        pk[i] = *(const float4*)&Kg[(size_t)row * HD + stc4];
        pv[i] = *(const float4*)&Vg[(size_t)row * HD + stc4];
    }

    for (int kt = 0; kt < ntiles; kt++) {
        __syncthreads();
        // stage prefetched K (hi+lo) and V tiles into smem
        #pragma unroll
        for (int i = 0; i < 4; i++) {
            const int row = strow + i * 16;
            uint32_t hx = f2tf(pk[i].x), hy = f2tf(pk[i].y),
                     hz = f2tf(pk[i].z), hw = f2tf(pk[i].w);
            *(uint4*)&Kh[row * KST + stc4] = make_uint4(hx, hy, hz, hw);
            *(uint4*)&Kl[row * KST + stc4] = make_uint4(
                f2tf(pk[i].x - __uint_as_float(hx)), f2tf(pk[i].y - __uint_as_float(hy)),
                f2tf(pk[i].z - __uint_as_float(hz)), f2tf(pk[i].w - __uint_as_float(hw)));
            *(uint4*)&Vs[row * VST + stc4] = make_uint4(f2tf(pv[i].x), f2tf(pv[i].y),
                                                        f2tf(pv[i].z), f2tf(pv[i].w));
        }
        __syncthreads();

        // prefetch next tile (latency covered by compute below)
        if (kt + 1 < ntiles) {
            #pragma unroll
            for (int i = 0; i < 4; i++) {
                const int row = (kt + 1) * 64 + strow + i * 16;
                pk[i] = *(const float4*)&Kg[(size_t)row * HD + stc4];
                pv[i] = *(const float4*)&Vg[(size_t)row * HD + stc4];
            }
        }

        // --- S = Q K^T (qh*kh + qh*kl) ---
        float sacc[8][4];
        #pragma unroll
        for (int nt = 0; nt < 8; nt++)
            #pragma unroll
            for (int r = 0; r < 4; r++) sacc[nt][r] = 0.f;

        #pragma unroll
        for (int kk = 0; kk < 8; kk++) {
            const uint32_t koff = kk * 32;
            uint32_t kb[8][2], lb[8][2];
            #pragma unroll
            for (int p = 0; p < 4; p++) {
                ldsm4(kb[2*p][0], kb[2*p][1], kb[2*p+1][0], kb[2*p+1][1], khb[p] + koff);
                ldsm4(lb[2*p][0], lb[2*p][1], lb[2*p+1][0], lb[2*p+1][1], klb[p] + koff);
            }
            #pragma unroll
            for (int nt = 0; nt < 8; nt++) {
                mma8(sacc[nt][0], sacc[nt][1], sacc[nt][2], sacc[nt][3],
                     qh[kk][0], qh[kk][1], qh[kk][2], qh[kk][3], kb[nt][0], kb[nt][1]);
                mma8(sacc[nt][0], sacc[nt][1], sacc[nt][2], sacc[nt][3],
                     qh[kk][0], qh[kk][1], qh[kk][2], qh[kk][3], lb[nt][0], lb[nt][1]);
            }
        }

        // --- scale + causal mask ---
        const bool may_mask = (kt * 64 + 63 > qbase);
        #pragma unroll
        for (int nt = 0; nt < 8; nt++) {
            const int c = kt * 64 + nt * 8 + 2 * lk;
            #pragma unroll
            for (int r = 0; r < 4; r++) sacc[nt][r] *= 0.125f;
            if (may_mask) {
                if (c     > r0)     sacc[nt][0] = -1e30f;
                if (c + 1 > r0)     sacc[nt][1] = -1e30f;
                if (c     > r0 + 8) sacc[nt][2] = -1e30f;
                if (c + 1 > r0 + 8) sacc[nt][3] = -1e30f;
            }
        }

        // --- online softmax (rows r0 and r0+8) ---
        float tm0 = -1e30f, tm1 = -1e30f;
        #pragma unroll
        for (int nt = 0; nt < 8; nt++) {
            tm0 = fmaxf(tm0, fmaxf(sacc[nt][0], sacc[nt][1]));
            tm1 = fmaxf(tm1, fmaxf(sacc[nt][2], sacc[nt][3]));
        }
        tm0 = fmaxf(tm0, __shfl_xor_sync(0xffffffff, tm0, 1));
        tm0 = fmaxf(tm0, __shfl_xor_sync(0xffffffff, tm0, 2));
        tm1 = fmaxf(tm1, __shfl_xor_sync(0xffffffff, tm1, 1));
        tm1 = fmaxf(tm1, __shfl_xor_sync(0xffffffff, tm1, 2));

        const float mn0 = fmaxf(m0, tm0);
        const float mn1 = fmaxf(m1, tm1);
        const float cor0 = __expf(m0 - mn0);
        const float cor1 = __expf(m1 - mn1);
        m0 = mn0; m1 = mn1;

        float sum0 = 0.f, sum1 = 0.f;
        #pragma unroll
        for (int nt = 0; nt < 8; nt++) {
            sacc[nt][0] = __expf(sacc[nt][0] - m0);
            sacc[nt][1] = __expf(sacc[nt][1] - m0);
            sacc[nt][2] = __expf(sacc[nt][2] - m1);
            sacc[nt][3] = __expf(sacc[nt][3] - m1);
            sum0 += sacc[nt][0] + sacc[nt][1];
            sum1 += sacc[nt][2] + sacc[nt][3];
        }
        sum0 += __shfl_xor_sync(0xffffffff, sum0, 1);
        sum0 += __shfl_xor_sync(0xffffffff, sum0, 2);
        sum1 += __shfl_xor_sync(0xffffffff, sum1, 1);
        sum1 += __shfl_xor_sync(0xffffffff, sum1, 2);
        l0 = l0 * cor0 + sum0;
        l1 = l1 * cor1 + sum1;

        #pragma unroll
        for (int nt = 0; nt < 8; nt++) {
            oacc[nt][0] *= cor0; oacc[nt][1] *= cor0;
            oacc[nt][2] *= cor1; oacc[nt][3] *= cor1;
        }

        // --- O += P V ---
        const int s0 = (lane & ~3) | (lk >> 1);   // src lane for cols lk
        const int s2 = s0 + 2;                    // src lane for cols lk+4
        const int par = lk & 1;
        #pragma unroll
        for (int kk = 0; kk < 8; kk++) {
            // rebuild A-fragment of P for this 8-key chunk via in-quad shuffles
            float v00 = __shfl_sync(0xffffffff, sacc[kk][0], s0);
            float v01 = __shfl_sync(0xffffffff, sacc[kk][1], s0);
            float v20 = __shfl_sync(0xffffffff, sacc[kk][0], s2);
            float v21 = __shfl_sync(0xffffffff, sacc[kk][1], s2);
            float v10 = __shfl_sync(0xffffffff, sacc[kk][2], s0);
            float v11 = __shfl_sync(0xffffffff, sacc[kk][3], s0);
            float v30 = __shfl_sync(0xffffffff, sacc[kk][2], s2);
            float v31 = __shfl_sync(0xffffffff, sacc[kk][3], s2);
            uint32_t a0 = f2tf(par ? v01 : v00);
            uint32_t a1 = f2tf(par ? v11 : v10);
            uint32_t a2 = f2tf(par ? v21 : v20);
            uint32_t a3 = f2tf(par ? v31 : v30);

            #pragma unroll
            for (int nt = 0; nt < 8; nt++) {
                uint32_t vb0 = Vs[(kk * 8 + lk) * VST + nt * 8 + lr];
                uint32_t vb1 = Vs[(kk * 8 + 4 + lk) * VST + nt * 8 + lr];
                mma8(oacc[nt][0], oacc[nt][1], oacc[nt][2], oacc[nt][3],
                     a0, a1, a2, a3, vb0, vb1);
            }
        }
    }

    // --- write O: [b, s, h*64 + d] ---
    const float inv0 = 1.f / l0;
    const float inv1 = 1.f / l1;
    float* Ob0 = O + ((size_t)b * SQ + r0) * DM + h * HD;
    float* Ob1 = O + ((size_t)b * SQ + r0 + 8) * DM + h * HD;
    #pragma unroll
    for (int nt = 0; nt < 8; nt++) {
        const int c = nt * 8 + 2 * lk;
        *(float2*)&Ob0[c] = make_float2(oacc[nt][0] * inv0, oacc[nt][1] * inv0);
        *(float2*)&Ob1[c] = make_float2(oacc[nt][2] * inv1, oacc[nt][3] * inv1);
    }
}

// ---------------------------------------------------------------------------
// Launch: 3 projection GEMMs -> TC flash attention -> output GEMM
// Inputs (metadata order): query, key, value, mask(unused; tril causal),
//   w_q, b_q, w_k, b_k, w_v, b_v, w_out, b_out
// ---------------------------------------------------------------------------
extern "C" void kernel_launch(void* const* d_in, const int* in_sizes, int n_in,
                              void* d_out, int out_size)
{
    const float* query = (const float*)d_in[0];
    const float* key   = (const float*)d_in[1];
    const float* value = (const float*)d_in[2];
    const float* w_q   = (const float*)d_in[4];
    const float* b_q   = (const float*)d_in[5];
    const float* w_k   = (const float*)d_in[6];
    const float* b_k   = (const float*)d_in[7];
    const float* w_v   = (const float*)d_in[8];
    const float* b_v   = (const float*)d_in[9];
    const float* w_out = (const float*)d_in[10];
    const float* b_out = (const float*)d_in[11];

    float *Qp, *Kp, *Vp, *Op;
    cudaGetSymbolAddress((void**)&Qp, g_Q);
    cudaGetSymbolAddress((void**)&Kp, g_K);
    cudaGetSymbolAddress((void**)&Vp, g_V);
    cudaGetSymbolAddress((void**)&Op, g_O);

    cudaFuncSetAttribute(attn_tc_kernel,
                         cudaFuncAttributeMaxDynamicSharedMemorySize, ATTN_SMEM);

    dim3 ggrid(DM / 128, MT / 128);   // (8, 32)
    gemm_tc_kernel<1><<<ggrid, 256>>>(query, w_q, b_q, Qp);
    gemm_tc_kernel<1><<<ggrid, 256>>>(key,   w_k, b_k, Kp);
    gemm_tc_kernel<1><<<ggrid, 256>>>(value, w_v, b_v, Vp);

    attn_tc_kernel<<<dim3(SQ / 128, NH, NB), 256, ATTN_SMEM>>>(Qp, Kp, Vp, Op);

    gemm_tc_kernel<0><<<ggrid, 256>>>(Op, w_out, b_out, (float*)d_out);
}